// round 12
// baseline (speedup 1.0000x reference)
#include <cuda_runtime.h>
#include <cstdint>

#define NNODE 16384
#define DFEAT 512
#define KTOP  16
#define BM 64
#define BN 64
#define BK 32
#define TPAD 68   // K-major tile row stride (floats)
#define SPAD 65   // sim tile stride
#define TKPAD 17  // topk list stride

// Scratch (allocation-free __device__ global, 32 MB)
__device__ __align__(16) float g_fn[NNODE * DFEAT];

// ---------------------------------------------------------------------------
// Kernel 1: XLA:GPU row-reduction emulation for nrm = sqrt(sum(x*x)), bit-exact
// candidate:
//   one warp per row; x2 vectorized (512 % 64 == 0 => vector_size 2)
//   lane t, iter i=0..7 ascending: e = (i*32 + t)*2
//     acc = add(acc, mul(x[e],x[e]));  acc = add(acc, mul(x[e+1],x[e+1]))
//   warp tree: acc = add(acc, shfl_down(acc, 16/8/4/2/1))
//   denom = add(sqrt_rn(acc), 1e-10f);  fn = div_rn(x, denom)
// All _rn intrinsics (immune to --use_fast_math).
// ---------------------------------------------------------------------------
__global__ void normalize_kernel(const float* __restrict__ f) {
    const int warp = threadIdx.x >> 5;
    const int lane = threadIdx.x & 31;
    const int row = blockIdx.x * 4 + warp;
    const float* src = f + (size_t)row * DFEAT;

    float acc = 0.f;
#pragma unroll
    for (int i = 0; i < 8; i++) {
        const float2 v = *(const float2*)(src + (((i << 5) + lane) << 1));
        acc = __fadd_rn(acc, __fmul_rn(v.x, v.x));
        acc = __fadd_rn(acc, __fmul_rn(v.y, v.y));
    }
#pragma unroll
    for (int off = 16; off > 0; off >>= 1)
        acc = __fadd_rn(acc, __shfl_down_sync(0xffffffffu, acc, off));

    float denom = __fadd_rn(__fsqrt_rn(acc), 1e-10f);
    denom = __shfl_sync(0xffffffffu, denom, 0);

    float* dst = g_fn + (size_t)row * DFEAT;
#pragma unroll
    for (int j = 0; j < 16; j++) {
        int idx = lane + (j << 5);
        dst[idx] = __fdiv_rn(src[idx], denom);
    }
}

// ---------------------------------------------------------------------------
// Kernel 2: fused sim-GEMM + per-row top-16.
// Each output element is a strict sequential k=0..511 ascending fused-FMA
// chain (single accumulator) — matching cuBLAS SIMT SGEMM accumulation.
// ---------------------------------------------------------------------------
__global__ __launch_bounds__(256) void simtopk_kernel(float* __restrict__ out) {
    __shared__ __align__(16) float atile[BK * TPAD];
    __shared__ __align__(16) float btile[BK * TPAD];
    __shared__ float sim[BM * SPAD];
    __shared__ float tv[BM * TKPAD];   // ascending: tv[r][0] = current threshold
    __shared__ int   ti[BM * TKPAD];

    const int tid = threadIdx.x;
    const int tx = tid & 15;
    const int ty = tid >> 4;
    const int rowbase = blockIdx.x * BM;

    for (int r = tid; r < BM; r += 256) {
#pragma unroll
        for (int p = 0; p < KTOP; p++) {
            tv[r * TKPAD + p] = -3.0e38f;
            ti[r * TKPAD + p] = 0;
        }
    }

    const int k4  = tid & 7;
    const int rld = tid >> 3;

    for (int colbase = 0; colbase < NNODE; colbase += BN) {
        float acc[4][4];
#pragma unroll
        for (int i = 0; i < 4; i++)
#pragma unroll
            for (int j = 0; j < 4; j++) acc[i][j] = 0.f;

        for (int kk = 0; kk < DFEAT; kk += BK) {
            __syncthreads();
            {
                const int kb = k4 << 2;
                const float* gA = g_fn + (size_t)(rowbase + rld) * DFEAT + kk + kb;
                const float* gB = g_fn + (size_t)(colbase + rld) * DFEAT + kk + kb;
#pragma unroll
                for (int rr = 0; rr < BM; rr += 32) {
                    float4 va = *(const float4*)(gA + (size_t)rr * DFEAT);
                    float4 vb = *(const float4*)(gB + (size_t)rr * DFEAT);
                    int rc = rld + rr;
                    atile[(kb + 0) * TPAD + rc] = va.x;
                    atile[(kb + 1) * TPAD + rc] = va.y;
                    atile[(kb + 2) * TPAD + rc] = va.z;
                    atile[(kb + 3) * TPAD + rc] = va.w;
                    btile[(kb + 0) * TPAD + rc] = vb.x;
                    btile[(kb + 1) * TPAD + rc] = vb.y;
                    btile[(kb + 2) * TPAD + rc] = vb.z;
                    btile[(kb + 3) * TPAD + rc] = vb.w;
                }
            }
            __syncthreads();
            // k ascending within tile; tiles ascending -> strict sequential chain
#pragma unroll
            for (int k = 0; k < BK; k++) {
                float4 a = *(const float4*)(atile + k * TPAD + (ty << 2));
                float4 b = *(const float4*)(btile + k * TPAD + (tx << 2));
                acc[0][0] = fmaf(a.x, b.x, acc[0][0]);
                acc[0][1] = fmaf(a.x, b.y, acc[0][1]);
                acc[0][2] = fmaf(a.x, b.z, acc[0][2]);
                acc[0][3] = fmaf(a.x, b.w, acc[0][3]);
                acc[1][0] = fmaf(a.y, b.x, acc[1][0]);
                acc[1][1] = fmaf(a.y, b.y, acc[1][1]);
                acc[1][2] = fmaf(a.y, b.z, acc[1][2]);
                acc[1][3] = fmaf(a.y, b.w, acc[1][3]);
                acc[2][0] = fmaf(a.z, b.x, acc[2][0]);
                acc[2][1] = fmaf(a.z, b.y, acc[2][1]);
                acc[2][2] = fmaf(a.z, b.z, acc[2][2]);
                acc[2][3] = fmaf(a.z, b.w, acc[2][3]);
                acc[3][0] = fmaf(a.w, b.x, acc[3][0]);
                acc[3][1] = fmaf(a.w, b.y, acc[3][1]);
                acc[3][2] = fmaf(a.w, b.z, acc[3][2]);
                acc[3][3] = fmaf(a.w, b.w, acc[3][3]);
            }
        }
        __syncthreads();
#pragma unroll
        for (int i = 0; i < 4; i++)
#pragma unroll
            for (int j = 0; j < 4; j++)
                sim[((ty << 2) + i) * SPAD + (tx << 2) + j] = acc[i][j];
        __syncthreads();

        // top-k update: one thread per row, ascending column order
        if (tid < BM) {
            const int r = tid;
            const int grow = rowbase + r;
            float* tvr = tv + r * TKPAD;
            int*   tir = ti + r * TKPAD;
            float thr = tvr[0];
#pragma unroll 1
            for (int c = 0; c < BN; c++) {
                float v = sim[r * SPAD + c];
                int j = colbase + c;
                if (v > thr && j != grow) {
                    int p = 0;
#pragma unroll 1
                    while (p < KTOP - 1 && tvr[p + 1] < v) {
                        tvr[p] = tvr[p + 1];
                        tir[p] = tir[p + 1];
                        p++;
                    }
                    tvr[p] = v;
                    tir[p] = j;
                    thr = tvr[0];
                }
            }
        }
        __syncthreads();
    }

    // Emit edge_index as float32 (indices < 2^24 exact):
    // out[0:N*K] = row ids, out[N*K:2*N*K] = neighbor ids, descending similarity.
    if (tid < BM) {
        const int r = tid;
        const int grow = rowbase + r;
        float* orow = out + grow * KTOP;
        float* ocol = out + NNODE * KTOP + grow * KTOP;
#pragma unroll
        for (int q = 0; q < KTOP; q++) {
            orow[q] = (float)grow;
            ocol[q] = (float)ti[r * TKPAD + (KTOP - 1 - q)];
        }
    }
}

// ---------------------------------------------------------------------------
extern "C" void kernel_launch(void* const* d_in, const int* in_sizes, int n_in,
                              void* d_out, int out_size) {
    const float* feature = (const float*)d_in[0];
    for (int i = 0; i < n_in; i++) {
        if (in_sizes[i] == NNODE * DFEAT) { feature = (const float*)d_in[i]; break; }
    }
    float* out = (float*)d_out;   // [2, 16384*16] compared as float32

    normalize_kernel<<<NNODE / 4, 128>>>(feature);
    simtopk_kernel<<<NNODE / BM, 256>>>(out);
}

// round 13
// speedup vs baseline: 1.1840x; 1.1840x over previous
#include <cuda_runtime.h>
#include <cstdint>

#define NNODE 16384
#define DFEAT 512
#define KTOP  16
#define BM 128
#define BN 128
#define BK 32
#define TPAD 132  // tile row stride (floats), mult of 4
#define SPAD 65   // sim half-tile stride (64 cols + 1)
#define TKPAD 17  // topk list stride

// Scratch (allocation-free __device__ global, 32 MB)
__device__ __align__(16) float g_fn[NNODE * DFEAT];

// ---- packed f32x2 helpers (each lane is an independent IEEE fp32 op -> the
// per-element fmaf chain is bit-identical to scalar fmaf) ----
__device__ __forceinline__ unsigned long long f32x2_fma(
    unsigned long long a, unsigned long long b, unsigned long long c) {
    unsigned long long d;
    asm("fma.rn.f32x2 %0, %1, %2, %3;" : "=l"(d) : "l"(a), "l"(b), "l"(c));
    return d;
}
__device__ __forceinline__ unsigned long long f32x2_splat(float x) {
    unsigned long long d;
    asm("mov.b64 %0, {%1, %2};" : "=l"(d) : "f"(x), "f"(x));
    return d;
}
__device__ __forceinline__ void f32x2_unpack(unsigned long long v, float& lo, float& hi) {
    asm("mov.b64 {%0, %1}, %2;" : "=f"(lo), "=f"(hi) : "l"(v));
}

// ---------------------------------------------------------------------------
// Kernel 1 (FROZEN — bit-matches the reference, rel_err = 0):
// XLA:GPU row reduction, one warp/row, x2-vectorized, shfl_down tree,
// sqrt_rn + 1e-10, div_rn.
// ---------------------------------------------------------------------------
__global__ void normalize_kernel(const float* __restrict__ f) {
    const int warp = threadIdx.x >> 5;
    const int lane = threadIdx.x & 31;
    const int row = blockIdx.x * 4 + warp;
    const float* src = f + (size_t)row * DFEAT;

    float acc = 0.f;
#pragma unroll
    for (int i = 0; i < 8; i++) {
        const float2 v = *(const float2*)(src + (((i << 5) + lane) << 1));
        acc = __fadd_rn(acc, __fmul_rn(v.x, v.x));
        acc = __fadd_rn(acc, __fmul_rn(v.y, v.y));
    }
#pragma unroll
    for (int off = 16; off > 0; off >>= 1)
        acc = __fadd_rn(acc, __shfl_down_sync(0xffffffffu, acc, off));

    float denom = __fadd_rn(__fsqrt_rn(acc), 1e-10f);
    denom = __shfl_sync(0xffffffffu, denom, 0);

    float* dst = g_fn + (size_t)row * DFEAT;
#pragma unroll
    for (int j = 0; j < 16; j++) {
        int idx = lane + (j << 5);
        dst[idx] = __fdiv_rn(src[idx], denom);
    }
}

// ---------------------------------------------------------------------------
// Kernel 2: fused sim-GEMM + per-row top-16.
// 128x128 CTA tile, 256 threads, 8x8 micro-tile via packed f32x2 FMA.
// Per-element accumulation: strict ascending-k fp32 fmaf chain (frozen bits).
// Top-k consumed in two 64-column halves in global ascending column order
// (identical comparisons/tie-breaks to the verified kernel).
// ---------------------------------------------------------------------------
extern __shared__ float dynsmem[];

__global__ __launch_bounds__(256) void simtopk_kernel(float* __restrict__ out) {
    float* atile = dynsmem;                       // [BK][TPAD]
    float* btile = atile + BK * TPAD;             // [BK][TPAD]
    float* sim   = btile + BK * TPAD;             // [BM][SPAD]  (64-col half)
    float* tv    = sim + BM * SPAD;               // [BM][TKPAD]
    int*   ti    = (int*)(tv + BM * TKPAD);       // [BM][TKPAD]

    const int tid = threadIdx.x;
    const int tx = tid & 15;        // 8 cols each: cols tx*8 .. tx*8+7
    const int ty = tid >> 4;        // 8 rows each: rows ty*8 .. ty*8+7
    const int rowbase = blockIdx.x * BM;

    for (int r = tid; r < BM; r += 256) {
#pragma unroll
        for (int p = 0; p < KTOP; p++) {
            tv[r * TKPAD + p] = -3.0e38f;
            ti[r * TKPAD + p] = 0;
        }
    }

    const int k4  = tid & 7;    // float4 chunk within BK (BK/4 = 8)
    const int rld = tid >> 3;   // 0..31 base row for loads

    for (int colbase = 0; colbase < NNODE; colbase += BN) {
        // 8x8 accumulators as 4 row-pairs x 8 cols of packed f32x2
        unsigned long long acc2[4][8];
#pragma unroll
        for (int i = 0; i < 4; i++)
#pragma unroll
            for (int j = 0; j < 8; j++) acc2[i][j] = 0ull;

        for (int kk = 0; kk < DFEAT; kk += BK) {
            __syncthreads();
            {
                const int kb = k4 << 2;
                const float* gA = g_fn + (size_t)(rowbase + rld) * DFEAT + kk + kb;
                const float* gB = g_fn + (size_t)(colbase + rld) * DFEAT + kk + kb;
#pragma unroll
                for (int rr = 0; rr < BM; rr += 32) {
                    float4 va = *(const float4*)(gA + (size_t)rr * DFEAT);
                    float4 vb = *(const float4*)(gB + (size_t)rr * DFEAT);
                    int rc = rld + rr;
                    atile[(kb + 0) * TPAD + rc] = va.x;
                    atile[(kb + 1) * TPAD + rc] = va.y;
                    atile[(kb + 2) * TPAD + rc] = va.z;
                    atile[(kb + 3) * TPAD + rc] = va.w;
                    btile[(kb + 0) * TPAD + rc] = vb.x;
                    btile[(kb + 1) * TPAD + rc] = vb.y;
                    btile[(kb + 2) * TPAD + rc] = vb.z;
                    btile[(kb + 3) * TPAD + rc] = vb.w;
                }
            }
            __syncthreads();
#pragma unroll
            for (int k = 0; k < BK; k++) {
                // A rows ty*8..+7: two LDS.128 = 4 packed row-pairs (already paired!)
                const ulonglong2 ap0 = *(const ulonglong2*)(atile + k * TPAD + (ty << 3));
                const ulonglong2 ap1 = *(const ulonglong2*)(atile + k * TPAD + (ty << 3) + 4);
                const float4 b0 = *(const float4*)(btile + k * TPAD + (tx << 3));
                const float4 b1 = *(const float4*)(btile + k * TPAD + (tx << 3) + 4);
                unsigned long long a2[4] = { ap0.x, ap0.y, ap1.x, ap1.y };
                unsigned long long sb[8] = {
                    f32x2_splat(b0.x), f32x2_splat(b0.y), f32x2_splat(b0.z), f32x2_splat(b0.w),
                    f32x2_splat(b1.x), f32x2_splat(b1.y), f32x2_splat(b1.z), f32x2_splat(b1.w)
                };
#pragma unroll
                for (int i = 0; i < 4; i++)
#pragma unroll
                    for (int j = 0; j < 8; j++)
                        acc2[i][j] = f32x2_fma(a2[i], sb[j], acc2[i][j]);
            }
        }

        // consume the 128x128 tile in two 64-column halves, ascending col order
#pragma unroll
        for (int h = 0; h < 2; h++) {
            __syncthreads();
            if ((tx >> 3) == h) {
                const int cb = (tx & 7) << 3;   // col within half
#pragma unroll
                for (int i = 0; i < 4; i++)
#pragma unroll
                    for (int j = 0; j < 8; j++) {
                        float lo, hi;
                        f32x2_unpack(acc2[i][j], lo, hi);
                        sim[((ty << 3) + (i << 1) + 0) * SPAD + cb + j] = lo;
                        sim[((ty << 3) + (i << 1) + 1) * SPAD + cb + j] = hi;
                    }
            }
            __syncthreads();

            if (tid < BM) {
                const int r = tid;
                const int grow = rowbase + r;
                const int cb0 = colbase + h * 64;
                float* tvr = tv + r * TKPAD;
                int*   tir = ti + r * TKPAD;
                float thr = tvr[0];
#pragma unroll 1
                for (int c = 0; c < 64; c++) {
                    float v = sim[r * SPAD + c];
                    int j = cb0 + c;
                    if (v > thr && j != grow) {
                        int p = 0;
#pragma unroll 1
                        while (p < KTOP - 1 && tvr[p + 1] < v) {
                            tvr[p] = tvr[p + 1];
                            tir[p] = tir[p + 1];
                            p++;
                        }
                        tvr[p] = v;
                        tir[p] = j;
                        thr = tvr[0];
                    }
                }
            }
        }
        __syncthreads();
    }

    // Emit edge_index as float32 (indices < 2^24 exact):
    // out[0:N*K] = row ids, out[N*K:2*N*K] = neighbor ids, descending similarity.
    if (tid < BM) {
        const int r = tid;
        const int grow = rowbase + r;
        float* orow = out + grow * KTOP;
        float* ocol = out + NNODE * KTOP + grow * KTOP;
#pragma unroll
        for (int q = 0; q < KTOP; q++) {
            orow[q] = (float)grow;
            ocol[q] = (float)ti[r * TKPAD + (KTOP - 1 - q)];
        }
    }
}

// ---------------------------------------------------------------------------
extern "C" void kernel_launch(void* const* d_in, const int* in_sizes, int n_in,
                              void* d_out, int out_size) {
    const float* feature = (const float*)d_in[0];
    for (int i = 0; i < n_in; i++) {
        if (in_sizes[i] == NNODE * DFEAT) { feature = (const float*)d_in[i]; break; }
    }
    float* out = (float*)d_out;   // [2, 16384*16] compared as float32

    const int smem_bytes = (BK * TPAD * 2 + BM * SPAD + BM * TKPAD) * 4
                         + BM * TKPAD * 4;
    cudaFuncSetAttribute(simtopk_kernel,
                         cudaFuncAttributeMaxDynamicSharedMemorySize, smem_bytes);

    normalize_kernel<<<NNODE / 4, 128>>>(feature);
    simtopk_kernel<<<NNODE / BM, 256, smem_bytes>>>(out);
}

// round 15
// speedup vs baseline: 1.7285x; 1.4598x over previous
#include <cuda_runtime.h>
#include <cstdint>

#define NNODE 16384
#define DFEAT 512
#define KTOP  16
#define BM 64
#define BN 256
#define BK 32
#define SPAD 65    // sim chunk stride (64 cols + 1): conflict-free topk reads
#define TKPAD 17
#define STAGE_F (BK * BM + BK * BN)          // 10240 floats per pipeline stage
#define NCT (NNODE / BN)                     // 64 column tiles
#define NKI (DFEAT / BK)                     // 16 k-tiles per column tile
#define NKT (NCT * NKI)                      // 1024 total k-tiles

// Transposed normalized features: g_fnT[k][node]  (allocation-free scratch)
__device__ __align__(16) float g_fnT[(size_t)DFEAT * NNODE];

// ---- packed f32x2 helpers: each lane is an independent IEEE fp32 fmaf, so the
// per-element ascending-k chain is bit-identical to scalar fmaf ----
__device__ __forceinline__ unsigned long long f32x2_fma(
    unsigned long long a, unsigned long long b, unsigned long long c) {
    unsigned long long d;
    asm("fma.rn.f32x2 %0, %1, %2, %3;" : "=l"(d) : "l"(a), "l"(b), "l"(c));
    return d;
}
__device__ __forceinline__ unsigned long long f32x2_splat(float x) {
    unsigned long long d;
    asm("mov.b64 %0, {%1, %2};" : "=l"(d) : "f"(x), "f"(x));
    return d;
}
__device__ __forceinline__ void f32x2_unpack(unsigned long long v, float& lo, float& hi) {
    asm("mov.b64 {%0, %1}, %2;" : "=f"(lo), "=f"(hi) : "l"(v));
}
__device__ __forceinline__ void cp16(uint32_t saddr, const float* g) {
    asm volatile("cp.async.cg.shared.global [%0], [%1], 16;"
                 :: "r"(saddr), "l"(g) : "memory");
}

// ---------------------------------------------------------------------------
// Kernel 1 (FROZEN arithmetic — bit-matches reference, rel_err = 0):
// XLA:GPU row reduce: one warp/row, x2-vectorized, shfl_down tree,
// sqrt_rn + 1e-10, div_rn. Output stored TRANSPOSED (values unchanged).
// ---------------------------------------------------------------------------
__global__ void normalize_kernel(const float* __restrict__ f) {
    const int warp = threadIdx.x >> 5;
    const int lane = threadIdx.x & 31;
    const int row = blockIdx.x * 4 + warp;
    const float* src = f + (size_t)row * DFEAT;

    float acc = 0.f;
#pragma unroll
    for (int i = 0; i < 8; i++) {
        const float2 v = *(const float2*)(src + (((i << 5) + lane) << 1));
        acc = __fadd_rn(acc, __fmul_rn(v.x, v.x));
        acc = __fadd_rn(acc, __fmul_rn(v.y, v.y));
    }
#pragma unroll
    for (int off = 16; off > 0; off >>= 1)
        acc = __fadd_rn(acc, __shfl_down_sync(0xffffffffu, acc, off));

    float denom = __fadd_rn(__fsqrt_rn(acc), 1e-10f);
    denom = __shfl_sync(0xffffffffu, denom, 0);

#pragma unroll
    for (int j = 0; j < 16; j++) {
        int idx = lane + (j << 5);
        g_fnT[(size_t)idx * NNODE + row] = __fdiv_rn(src[idx], denom);
    }
}

// ---------------------------------------------------------------------------
// Kernel 2: fused sim-GEMM + per-row top-16.
// 64x256 CTA tile, 256 threads, 8x8 micro-tile (rows 8ty..+7; cols
// {4tx..+3, 128+4tx..+3}), packed f32x2 FMA, cp.async 2-stage pipeline.
// WAR-safe: barrier after compute before the stage is re-filled.
// ---------------------------------------------------------------------------
extern __shared__ float smem[];

__device__ __forceinline__ void issue_tile(int t, int tid, int rowbase, uint32_t sbase) {
    const int colbase = (t >> 4) * BN;
    const int kk = (t & 15) * BK;
    const uint32_t abase = sbase + (uint32_t)((t & 1) * STAGE_F) * 4u;
    const uint32_t bbase = abase + (uint32_t)(BK * BM) * 4u;
#pragma unroll
    for (int j = 0; j < 2; j++) {               // A: 512 x 16B chunks
        int idx = tid + (j << 8);
        int k = idx >> 4, o = idx & 15;
        cp16(abase + (uint32_t)(k * BM + (o << 2)) * 4u,
             g_fnT + (size_t)(kk + k) * NNODE + rowbase + (o << 2));
    }
#pragma unroll
    for (int j = 0; j < 8; j++) {               // B: 2048 x 16B chunks
        int idx = tid + (j << 8);
        int k = idx >> 6, o = idx & 63;
        cp16(bbase + (uint32_t)(k * BN + (o << 2)) * 4u,
             g_fnT + (size_t)(kk + k) * NNODE + colbase + (o << 2));
    }
    asm volatile("cp.async.commit_group;" ::: "memory");
}

__global__ __launch_bounds__(256, 2) void simtopk_kernel(float* __restrict__ out) {
    float* tiles = smem;                        // 2 stages x (A + B)
    float* sim   = smem + 2 * STAGE_F;          // [BM][SPAD] 64-col chunk
    float* tv    = sim + BM * SPAD;             // [BM][TKPAD]
    int*   ti    = (int*)(tv + BM * TKPAD);

    const int tid = threadIdx.x;
    const int tx = tid & 31;                    // col group
    const int ty = tid >> 5;                    // row group == warp id (A broadcast)
    const int rowbase = blockIdx.x * BM;
    const uint32_t sbase = (uint32_t)__cvta_generic_to_shared(smem);

    for (int r = tid; r < BM; r += 256) {
#pragma unroll
        for (int p = 0; p < KTOP; p++) {
            tv[r * TKPAD + p] = -3.0e38f;
            ti[r * TKPAD + p] = 0;
        }
    }

    issue_tile(0, tid, rowbase, sbase);

    for (int ct = 0; ct < NCT; ct++) {
        unsigned long long acc2[4][8];
#pragma unroll
        for (int i = 0; i < 4; i++)
#pragma unroll
            for (int j = 0; j < 8; j++) acc2[i][j] = 0ull;

        for (int ki = 0; ki < NKI; ki++) {
            const int t = ct * NKI + ki;
            if (t + 1 < NKT) {
                issue_tile(t + 1, tid, rowbase, sbase);
                asm volatile("cp.async.wait_group 1;" ::: "memory");
            } else {
                asm volatile("cp.async.wait_group 0;" ::: "memory");
            }
            __syncthreads();

            const float* A = tiles + (t & 1) * STAGE_F;
            const float* B = A + BK * BM;
#pragma unroll
            for (int k = 0; k < BK; k++) {
                const ulonglong2 ap0 = *(const ulonglong2*)(A + k * BM + (ty << 3));
                const ulonglong2 ap1 = *(const ulonglong2*)(A + k * BM + (ty << 3) + 4);
                const float4 b0 = *(const float4*)(B + k * BN + (tx << 2));
                const float4 b1 = *(const float4*)(B + k * BN + 128 + (tx << 2));
                unsigned long long a2[4] = { ap0.x, ap0.y, ap1.x, ap1.y };
                unsigned long long sb[8] = {
                    f32x2_splat(b0.x), f32x2_splat(b0.y),
                    f32x2_splat(b0.z), f32x2_splat(b0.w),
                    f32x2_splat(b1.x), f32x2_splat(b1.y),
                    f32x2_splat(b1.z), f32x2_splat(b1.w)
                };
#pragma unroll
                for (int i = 0; i < 4; i++)
#pragma unroll
                    for (int j = 0; j < 8; j++)
                        acc2[i][j] = f32x2_fma(a2[i], sb[j], acc2[i][j]);
            }
            // WAR fence: stage (t&1) is re-filled by issue_tile(t+2) at the top
            // of the next iteration — every warp must be done reading it first.
            __syncthreads();
        }

        // consume 256 columns in four 64-col chunks, ascending global order
        const int colbase = ct * BN;
#pragma unroll
        for (int h = 0; h < 4; h++) {
            __syncthreads();
            const int j0 = (h < 2) ? 0 : 4;
            const bool active = (tx >> 4) == (h & 1);
            if (active) {
                const int cbl = (tx << 2) & 63;
#pragma unroll
                for (int i = 0; i < 4; i++) {
                    float* rlo = sim + ((ty << 3) + (i << 1)) * SPAD + cbl;
                    float* rhi = rlo + SPAD;
#pragma unroll
                    for (int jj = 0; jj < 4; jj++) {
                        float lo, hi;
                        f32x2_unpack(acc2[i][j0 + jj], lo, hi);
                        rlo[jj] = lo;
                        rhi[jj] = hi;
                    }
                }
            }
            __syncthreads();

            if (tid < BM) {
                const int r = tid;
                const int grow = rowbase + r;
                const int cb0 = colbase + (h << 6);
                float* tvr = tv + r * TKPAD;
                int*   tir = ti + r * TKPAD;
                float thr = tvr[0];
#pragma unroll 1
                for (int c = 0; c < 64; c++) {
                    float v = sim[r * SPAD + c];
                    int j = cb0 + c;
                    if (v > thr && j != grow) {
                        int p = 0;
#pragma unroll 1
                        while (p < KTOP - 1 && tvr[p + 1] < v) {
                            tvr[p] = tvr[p + 1];
                            tir[p] = tir[p + 1];
                            p++;
                        }
                        tvr[p] = v;
                        tir[p] = j;
                        thr = tvr[0];
                    }
                }
            }
        }
    }

    __syncthreads();
    // Emit edge_index as float32 (indices < 2^24 exact):
    // out[0:N*K] = row ids, out[N*K:2*N*K] = neighbor ids, descending similarity.
    if (tid < BM) {
        const int r = tid;
        const int grow = rowbase + r;
        float* orow = out + grow * KTOP;
        float* ocol = out + NNODE * KTOP + grow * KTOP;
#pragma unroll
        for (int q = 0; q < KTOP; q++) {
            orow[q] = (float)grow;
            ocol[q] = (float)ti[r * TKPAD + (KTOP - 1 - q)];
        }
    }
}

// ---------------------------------------------------------------------------
extern "C" void kernel_launch(void* const* d_in, const int* in_sizes, int n_in,
                              void* d_out, int out_size) {
    const float* feature = (const float*)d_in[0];
    for (int i = 0; i < n_in; i++) {
        if (in_sizes[i] == NNODE * DFEAT) { feature = (const float*)d_in[i]; break; }
    }
    float* out = (float*)d_out;   // [2, 16384*16] compared as float32

    const int smem_bytes = (2 * STAGE_F + BM * SPAD + BM * TKPAD) * 4
                         + BM * TKPAD * 4;     // 107,264 B
    cudaFuncSetAttribute(simtopk_kernel,
                         cudaFuncAttributeMaxDynamicSharedMemorySize, smem_bytes);

    normalize_kernel<<<NNODE / 4, 128>>>(feature);
    simtopk_kernel<<<NNODE / BM, 256, smem_bytes>>>(out);
}